// round 14
// baseline (speedup 1.0000x reference)
#include <cuda_runtime.h>
#include <math.h>

// Problem constants (fixed by the dataset)
#define NPTS 65536
#define CH   128
#define NCLS 10
#define KNBR 27
#define OUTC 17   // 1 (ctr) + 6 (reg) + 10 (cls)

// sigmoid(s) > 0.15  <=>  s > log(0.15/0.85)
#define THRESH_LOGIT -1.7346010553881064f

#define NBLOCKS 1184               // 148 SMs x 8 resident blocks: ONE wave
#define NGROUPS (NPTS / 32)        // 2048 sem groups of 32 points
#define MAXG 2                     // groups per block (<= ceil(2048/1184))
#define STORE_TOTAL (NBLOCKS * 256)

__device__ __forceinline__ float elu1(float x) {
    return x > 0.f ? x : (expf(x) - 1.f);
}

// packed f32x2 FMA (sm_103a): d = a*b + d
__device__ __forceinline__ void ffma2(float2& d, float2 a, float2 b) {
    unsigned long long ud = *reinterpret_cast<unsigned long long*>(&d);
    const unsigned long long ua = *reinterpret_cast<const unsigned long long*>(&a);
    const unsigned long long ub = *reinterpret_cast<const unsigned long long*>(&b);
    asm("fma.rn.f32x2 %0, %1, %2, %0;" : "+l"(ud) : "l"(ua), "l"(ub));
    d = *reinterpret_cast<float2*>(&ud);
}

// ---------------------------------------------------------------------------
// Fused kernel (single-wave variant of the R12/R13 winner). Warp 0: sem for
// 1-2 groups of 32 points (lane-owns-point, direct LDG rows, untransposed
// smem weights read as broadcast LDS.64 -> FFMA2), then joins the store pool.
// Warps 1-7: global-stride float4 zero-fill from the start. Grid = one full
// residency wave so every block runs from t=0 (no ragged second wave).
// ---------------------------------------------------------------------------
__global__ void __launch_bounds__(256)
k_fused(const float* __restrict__ feats,
        const int*   __restrict__ nbr,
        const float* __restrict__ Wsem,
        const float* __restrict__ bsem,
        const float* __restrict__ fo_w,
        const float* __restrict__ fo_g,
        const float* __restrict__ fo_b,
        const float* __restrict__ cls_out_w,
        const float* __restrict__ cls_out_g,
        const float* __restrict__ cls_out_b,
        const float* __restrict__ up_w,
        const float* __restrict__ up_g,
        const float* __restrict__ up_b,
        const float* __restrict__ fuse_w,
        const float* __restrict__ fuse_g,
        const float* __restrict__ fuse_b,
        const float* __restrict__ exp_w,
        const float* __restrict__ exp_g,
        const float* __restrict__ exp_b,
        const float* __restrict__ ctr_w,
        const float* __restrict__ reg_w,
        const float* __restrict__ cls_w,
        const float* __restrict__ cls_b,
        const float* __restrict__ scales,
        float* __restrict__ out,
        long long nelem) {
    __shared__ __align__(16) float sW[NCLS * CH];   // Wsem as-is [m][c], 5KB
    __shared__ float sThr[NCLS];
    __shared__ unsigned short smask[MAXG * 32];
    // head-pipeline scratch (rare path only)
    __shared__ float sx[CH];
    __shared__ float cat[2 * CH];
    __shared__ float sec[CH];
    __shared__ float sof[CH];

    const int tid  = threadIdx.x;
    const int wid  = tid >> 5;
    const int lane = tid & 31;
    const int b    = blockIdx.x;
    const long long n4 = nelem >> 2;
    const int ngrp = (b < NGROUPS - NBLOCKS) ? 2 : 1;   // groups this block owns

    unsigned mymask = 0;

    if (wid == 0) {
        // ================= sem warp =================
        // stage weights verbatim (coalesced float4 copy; no transpose)
        const float4* Wf4 = reinterpret_cast<const float4*>(Wsem);
        float4* sWf4 = reinterpret_cast<float4*>(sW);
#pragma unroll
        for (int k = 0; k < (NCLS * CH / 4) / 32; k++)        // 10 iters
            sWf4[k * 32 + lane] = Wf4[k * 32 + lane];
        if (lane < NCLS) sThr[lane] = THRESH_LOGIT - bsem[lane];
        __syncwarp();

        // grid-stride over sem groups: group g = b + i*NBLOCKS
        for (int i = 0; i < ngrp; i++) {
            const int g  = b + i * NBLOCKS;
            const int pt = g * 32 + lane;       // lane owns this point
            const float4* fp = reinterpret_cast<const float4*>(feats)
                               + (long long)pt * 32;
            float2 acc2[5];   // acc2[j] = (s_{2j}, s_{2j+1})
#pragma unroll
            for (int j = 0; j < 5; j++) acc2[j] = make_float2(0.f, 0.f);

#pragma unroll
            for (int it = 0; it < 8; it++) {
                const float4 f = fp[it];
                const float fv[4] = {f.x, f.y, f.z, f.w};
#pragma unroll
                for (int ch = 0; ch < 4; ch++) {
                    const float* wrow = sW + (it * 4 + ch) * NCLS;
                    const float2 a = make_float2(fv[ch], fv[ch]);
#pragma unroll
                    for (int j = 0; j < 5; j++) {
                        const float2 w2 = *reinterpret_cast<const float2*>(wrow + 2 * j);
                        ffma2(acc2[j], a, w2);               // broadcast LDS.64
                    }
                }
            }
            unsigned m = 0;
#pragma unroll
            for (int j = 0; j < 5; j++) {
                if (acc2[j].x > sThr[2 * j])     m |= (1u << (2 * j));
                if (acc2[j].y > sThr[2 * j + 1]) m |= (1u << (2 * j + 1));
            }
            smask[i * 32 + lane] = (unsigned short)m;
            mymask |= m;
        }
    }

    // ================= stores: all 256 threads (warp 0 arrives late) ========
    {
        float4* out4 = reinterpret_cast<float4*>(out);
        const float4 z = make_float4(0.f, 0.f, 0.f, 0.f);
        const long long sid = (long long)b * 256 + tid;
        for (long long t = sid; t < n4; t += STORE_TOTAL) out4[t] = z;
        // scalar tail safety (nelem % 4; exact dataset has none)
        for (long long s = (n4 << 2) + sid; s < nelem; s += STORE_TOTAL) out[s] = 0.f;
    }

    if (!__syncthreads_or((int)mymask)) return;   // hot path: exit

    // ---------------- rare path: full head pipeline for flagged pairs -------
    const int j = tid;   // channel id where j < CH
    for (int gi = 0; gi < ngrp; gi++) {
        const int blk_base = (b + gi * NBLOCKS) * 32;
        for (int t = 0; t < 32; t++) {
            unsigned m = smask[gi * 32 + t];
            if (!m) continue;
            const int i = blk_base + t;

            // offset_features[i] = ELU(affine(sum_k feats[nbr[i,k]] @ fo_w[k]))
            float acc = 0.f;
            for (int k = 0; k < KNBR; k++) {
                const int nb = nbr[i * KNBR + k];
                __syncthreads();
                if (j < CH) sx[j] = feats[(long long)nb * CH + j];
                __syncthreads();
                if (j < CH) {
                    const float* W = fo_w + (long long)k * CH * CH;
                    for (int mm = 0; mm < CH; mm++) acc += sx[mm] * W[mm * CH + j];
                }
            }
            if (j < CH) sof[j] = elu1(acc * fo_g[j] + fo_b[j]);

            while (m) {
                const int c = __ffs(m) - 1;
                m &= (m - 1);
                for (int half = 0; half < 2; half++) {
                    __syncthreads();
                    if (j < CH) sx[j] = (half == 0) ? sof[j]
                                                    : feats[(long long)i * CH + j];
                    __syncthreads();
                    if (j < CH) {   // hc
                        const float* W = cls_out_w + (long long)c * CH * CH;
                        float a = 0.f;
                        for (int mm = 0; mm < CH; mm++) a += sx[mm] * W[mm * CH + j];
                        a = a * cls_out_g[c * CH + j] + cls_out_b[c * CH + j];
                        cat[j] = elu1(a);
                    }
                    __syncthreads();
                    if (j < CH) {   // uc
                        const float* W = up_w + (long long)c * CH * CH;
                        float a = 0.f;
                        for (int mm = 0; mm < CH; mm++) a += cat[mm] * W[mm * CH + j];
                        a = a * up_g[c * CH + j] + up_b[c * CH + j];
                        cat[CH + j] = elu1(a);
                    }
                    __syncthreads();
                    float fc = 0.f;
                    if (j < CH) {   // fc
                        const float* W = fuse_w + (long long)c * 2 * CH * CH;
                        float a = 0.f;
                        for (int mm = 0; mm < 2 * CH; mm++) a += cat[mm] * W[mm * CH + j];
                        a = a * fuse_g[c * CH + j] + fuse_b[c * CH + j];
                        fc = elu1(a);
                    }
                    __syncthreads();
                    if (j < CH) sx[j] = fc;
                    __syncthreads();
                    if (j < CH) {   // ec
                        const float* W = exp_w + (long long)c * CH * CH;
                        float a = 0.f;
                        for (int mm = 0; mm < CH; mm++) a += sx[mm] * W[mm * CH + j];
                        a = a * exp_g[c * CH + j] + exp_b[c * CH + j];
                        sec[j] = elu1(a);
                    }
                    __syncthreads();

                    const long long row = (half == 0) ? (long long)i
                                                      : (long long)(NPTS + i);
                    float* orow = out + ((long long)c * 2 * NPTS + row) * OUTC;
                    if (j == 0) {
                        float s = 0.f;
                        for (int mm = 0; mm < CH; mm++) s += sec[mm] * ctr_w[mm];
                        orow[0] = s;
                    } else if (j < 7) {
                        const int r = j - 1;
                        float s = 0.f;
                        for (int mm = 0; mm < CH; mm++) s += sec[mm] * reg_w[mm * 6 + r];
                        orow[j] = expf(scales[c] * s);
                    } else if (j < 17) {
                        const int qq = j - 7;
                        float s = 0.f;
                        for (int mm = 0; mm < CH; mm++) s += sec[mm] * cls_w[mm * NCLS + qq];
                        orow[j] = s + cls_b[qq];
                    }
                }
            }
        }
    }
}

// ---------------------------------------------------------------------------
// Launch (single kernel, single stream: graph-capture safe).
// Input order per metadata: coords, feats, nbr, Wsem, bsem, off_w1,g1,b1,
// off_w2,g2,b2, off_w3, fo_w,g,b, cls_out_w,g,b, up_w,g,b, fuse_w,g,b,
// exp_w,g,b, ctr_w, reg_w, cls_w, cls_b, scales.
// Offset-MLP branch (5..11) and coords (0) are dead w.r.t. the output tensor.
// ---------------------------------------------------------------------------
extern "C" void kernel_launch(void* const* d_in, const int* in_sizes, int n_in,
                              void* d_out, int out_size) {
    const float* feats     = (const float*)d_in[1];
    const int*   nbr       = (const int*)  d_in[2];
    const float* Wsem      = (const float*)d_in[3];
    const float* bsem      = (const float*)d_in[4];
    const float* fo_w      = (const float*)d_in[12];
    const float* fo_g      = (const float*)d_in[13];
    const float* fo_b      = (const float*)d_in[14];
    const float* cls_out_w = (const float*)d_in[15];
    const float* cls_out_g = (const float*)d_in[16];
    const float* cls_out_b = (const float*)d_in[17];
    const float* up_w      = (const float*)d_in[18];
    const float* up_g      = (const float*)d_in[19];
    const float* up_b      = (const float*)d_in[20];
    const float* fuse_w    = (const float*)d_in[21];
    const float* fuse_g    = (const float*)d_in[22];
    const float* fuse_b    = (const float*)d_in[23];
    const float* exp_w     = (const float*)d_in[24];
    const float* exp_g     = (const float*)d_in[25];
    const float* exp_b     = (const float*)d_in[26];
    const float* ctr_w     = (const float*)d_in[27];
    const float* reg_w     = (const float*)d_in[28];
    const float* cls_w     = (const float*)d_in[29];
    const float* cls_b     = (const float*)d_in[30];
    const float* scales    = (const float*)d_in[31];
    float* out = (float*)d_out;

    const long long nelem = (long long)out_size;

    k_fused<<<NBLOCKS, 256>>>(feats, nbr, Wsem, bsem,
                              fo_w, fo_g, fo_b,
                              cls_out_w, cls_out_g, cls_out_b,
                              up_w, up_g, up_b,
                              fuse_w, fuse_g, fuse_b,
                              exp_w, exp_g, exp_b,
                              ctr_w, reg_w, cls_w, cls_b, scales,
                              out, nelem);
}

// round 15
// speedup vs baseline: 2.4213x; 2.4213x over previous
#include <cuda_runtime.h>
#include <math.h>

// Problem constants (fixed by the dataset)
#define NPTS 65536
#define CH   128
#define NCLS 10
#define KNBR 27
#define OUTC 17   // 1 (ctr) + 6 (reg) + 10 (cls)

// sigmoid(s) > 0.15  <=>  s > log(0.15/0.85)
#define THRESH_LOGIT -1.7346010553881064f

#define NBLOCKS 1024               // <= 7 blocks/SM: single fully-resident wave
#define PTS_PER_BLOCK 64           // warp 0: two fixed 32-point groups
#define STORE_TOTAL (NBLOCKS * 256)

__device__ __forceinline__ float elu1(float x) {
    return x > 0.f ? x : (expf(x) - 1.f);
}

// packed f32x2 FMA (sm_103a): d = a*b + d
__device__ __forceinline__ void ffma2(float2& d, float2 a, float2 b) {
    unsigned long long ud = *reinterpret_cast<unsigned long long*>(&d);
    const unsigned long long ua = *reinterpret_cast<const unsigned long long*>(&a);
    const unsigned long long ub = *reinterpret_cast<const unsigned long long*>(&b);
    asm("fma.rn.f32x2 %0, %1, %2, %0;" : "+l"(ud) : "l"(ua), "l"(ub));
    d = *reinterpret_cast<float2*>(&ud);
}

// ---------------------------------------------------------------------------
// Fused kernel (R12/R13 winner, single-wave, ALL loop bounds compile-time).
// Warp 0: sem for 2 fixed groups of 32 points (lane-owns-point, direct LDG
// rows, untransposed smem weights read as broadcast LDS.64 -> FFMA2), then
// joins the store pool. Warps 1-7: global-stride float4 zero-fill from t=0.
// ---------------------------------------------------------------------------
__global__ void __launch_bounds__(256)
k_fused(const float* __restrict__ feats,
        const int*   __restrict__ nbr,
        const float* __restrict__ Wsem,
        const float* __restrict__ bsem,
        const float* __restrict__ fo_w,
        const float* __restrict__ fo_g,
        const float* __restrict__ fo_b,
        const float* __restrict__ cls_out_w,
        const float* __restrict__ cls_out_g,
        const float* __restrict__ cls_out_b,
        const float* __restrict__ up_w,
        const float* __restrict__ up_g,
        const float* __restrict__ up_b,
        const float* __restrict__ fuse_w,
        const float* __restrict__ fuse_g,
        const float* __restrict__ fuse_b,
        const float* __restrict__ exp_w,
        const float* __restrict__ exp_g,
        const float* __restrict__ exp_b,
        const float* __restrict__ ctr_w,
        const float* __restrict__ reg_w,
        const float* __restrict__ cls_w,
        const float* __restrict__ cls_b,
        const float* __restrict__ scales,
        float* __restrict__ out,
        long long nelem) {
    __shared__ __align__(16) float sW[NCLS * CH];   // Wsem as-is [m][c], 5KB
    __shared__ float sThr[NCLS];
    __shared__ unsigned short smask[PTS_PER_BLOCK];
    // head-pipeline scratch (rare path only)
    __shared__ float sx[CH];
    __shared__ float cat[2 * CH];
    __shared__ float sec[CH];
    __shared__ float sof[CH];

    const int tid  = threadIdx.x;
    const int wid  = tid >> 5;
    const int lane = tid & 31;
    const int b    = blockIdx.x;
    const long long n4 = nelem >> 2;

    unsigned mymask = 0;

    if (wid == 0) {
        // ================= sem warp =================
        // stage weights verbatim (coalesced float4 copy; no transpose)
        const float4* Wf4 = reinterpret_cast<const float4*>(Wsem);
        float4* sWf4 = reinterpret_cast<float4*>(sW);
#pragma unroll
        for (int k = 0; k < (NCLS * CH / 4) / 32; k++)        // 10 iters
            sWf4[k * 32 + lane] = Wf4[k * 32 + lane];
        if (lane < NCLS) sThr[lane] = THRESH_LOGIT - bsem[lane];
        __syncwarp();

        // two FIXED groups: g = 0,1; lane owns point b*64 + g*32 + lane
#pragma unroll
        for (int g = 0; g < 2; g++) {
            const int pt = b * PTS_PER_BLOCK + g * 32 + lane;
            const float4* fp = reinterpret_cast<const float4*>(feats)
                               + (long long)pt * 32;
            float2 acc2[5];   // acc2[j] = (s_{2j}, s_{2j+1})
#pragma unroll
            for (int j = 0; j < 5; j++) acc2[j] = make_float2(0.f, 0.f);

#pragma unroll
            for (int it = 0; it < 8; it++) {
                const float4 f = fp[it];
                const float fv[4] = {f.x, f.y, f.z, f.w};
#pragma unroll
                for (int ch = 0; ch < 4; ch++) {
                    const float* wrow = sW + (it * 4 + ch) * NCLS;
                    const float2 a = make_float2(fv[ch], fv[ch]);
#pragma unroll
                    for (int j = 0; j < 5; j++) {
                        const float2 w2 = *reinterpret_cast<const float2*>(wrow + 2 * j);
                        ffma2(acc2[j], a, w2);               // broadcast LDS.64
                    }
                }
            }
            unsigned m = 0;
#pragma unroll
            for (int j = 0; j < 5; j++) {
                if (acc2[j].x > sThr[2 * j])     m |= (1u << (2 * j));
                if (acc2[j].y > sThr[2 * j + 1]) m |= (1u << (2 * j + 1));
            }
            smask[g * 32 + lane] = (unsigned short)m;
            mymask |= m;
        }
    }

    // ================= stores: all 256 threads (warp 0 arrives late) ========
    {
        float4* out4 = reinterpret_cast<float4*>(out);
        const float4 z = make_float4(0.f, 0.f, 0.f, 0.f);
        const long long sid = (long long)b * 256 + tid;
        for (long long t = sid; t < n4; t += STORE_TOTAL) out4[t] = z;
        // scalar tail safety (nelem % 4; exact dataset has none)
        for (long long s = (n4 << 2) + sid; s < nelem; s += STORE_TOTAL) out[s] = 0.f;
    }

    if (!__syncthreads_or((int)mymask)) return;   // hot path: exit

    // ---------------- rare path: full head pipeline for flagged pairs -------
    const int blk_base = b * PTS_PER_BLOCK;
    const int j = tid;   // channel id where j < CH
    for (int t = 0; t < PTS_PER_BLOCK; t++) {
        unsigned m = smask[t];
        if (!m) continue;
        const int i = blk_base + t;

        // offset_features[i] = ELU(affine(sum_k feats[nbr[i,k]] @ fo_w[k]))
        float acc = 0.f;
        for (int k = 0; k < KNBR; k++) {
            const int nb = nbr[i * KNBR + k];
            __syncthreads();
            if (j < CH) sx[j] = feats[(long long)nb * CH + j];
            __syncthreads();
            if (j < CH) {
                const float* W = fo_w + (long long)k * CH * CH;
                for (int mm = 0; mm < CH; mm++) acc += sx[mm] * W[mm * CH + j];
            }
        }
        if (j < CH) sof[j] = elu1(acc * fo_g[j] + fo_b[j]);

        while (m) {
            const int c = __ffs(m) - 1;
            m &= (m - 1);
            for (int half = 0; half < 2; half++) {
                __syncthreads();
                if (j < CH) sx[j] = (half == 0) ? sof[j]
                                                : feats[(long long)i * CH + j];
                __syncthreads();
                if (j < CH) {   // hc
                    const float* W = cls_out_w + (long long)c * CH * CH;
                    float a = 0.f;
                    for (int mm = 0; mm < CH; mm++) a += sx[mm] * W[mm * CH + j];
                    a = a * cls_out_g[c * CH + j] + cls_out_b[c * CH + j];
                    cat[j] = elu1(a);
                }
                __syncthreads();
                if (j < CH) {   // uc
                    const float* W = up_w + (long long)c * CH * CH;
                    float a = 0.f;
                    for (int mm = 0; mm < CH; mm++) a += cat[mm] * W[mm * CH + j];
                    a = a * up_g[c * CH + j] + up_b[c * CH + j];
                    cat[CH + j] = elu1(a);
                }
                __syncthreads();
                float fc = 0.f;
                if (j < CH) {   // fc
                    const float* W = fuse_w + (long long)c * 2 * CH * CH;
                    float a = 0.f;
                    for (int mm = 0; mm < 2 * CH; mm++) a += cat[mm] * W[mm * CH + j];
                    a = a * fuse_g[c * CH + j] + fuse_b[c * CH + j];
                    fc = elu1(a);
                }
                __syncthreads();
                if (j < CH) sx[j] = fc;
                __syncthreads();
                if (j < CH) {   // ec
                    const float* W = exp_w + (long long)c * CH * CH;
                    float a = 0.f;
                    for (int mm = 0; mm < CH; mm++) a += sx[mm] * W[mm * CH + j];
                    a = a * exp_g[c * CH + j] + exp_b[c * CH + j];
                    sec[j] = elu1(a);
                }
                __syncthreads();

                const long long row = (half == 0) ? (long long)i
                                                  : (long long)(NPTS + i);
                float* orow = out + ((long long)c * 2 * NPTS + row) * OUTC;
                if (j == 0) {
                    float s = 0.f;
                    for (int mm = 0; mm < CH; mm++) s += sec[mm] * ctr_w[mm];
                    orow[0] = s;
                } else if (j < 7) {
                    const int r = j - 1;
                    float s = 0.f;
                    for (int mm = 0; mm < CH; mm++) s += sec[mm] * reg_w[mm * 6 + r];
                    orow[j] = expf(scales[c] * s);
                } else if (j < 17) {
                    const int qq = j - 7;
                    float s = 0.f;
                    for (int mm = 0; mm < CH; mm++) s += sec[mm] * cls_w[mm * NCLS + qq];
                    orow[j] = s + cls_b[qq];
                }
            }
        }
    }
}

// ---------------------------------------------------------------------------
// Launch (single kernel, single stream: graph-capture safe).
// Input order per metadata: coords, feats, nbr, Wsem, bsem, off_w1,g1,b1,
// off_w2,g2,b2, off_w3, fo_w,g,b, cls_out_w,g,b, up_w,g,b, fuse_w,g,b,
// exp_w,g,b, ctr_w, reg_w, cls_w, cls_b, scales.
// Offset-MLP branch (5..11) and coords (0) are dead w.r.t. the output tensor.
// ---------------------------------------------------------------------------
extern "C" void kernel_launch(void* const* d_in, const int* in_sizes, int n_in,
                              void* d_out, int out_size) {
    const float* feats     = (const float*)d_in[1];
    const int*   nbr       = (const int*)  d_in[2];
    const float* Wsem      = (const float*)d_in[3];
    const float* bsem      = (const float*)d_in[4];
    const float* fo_w      = (const float*)d_in[12];
    const float* fo_g      = (const float*)d_in[13];
    const float* fo_b      = (const float*)d_in[14];
    const float* cls_out_w = (const float*)d_in[15];
    const float* cls_out_g = (const float*)d_in[16];
    const float* cls_out_b = (const float*)d_in[17];
    const float* up_w      = (const float*)d_in[18];
    const float* up_g      = (const float*)d_in[19];
    const float* up_b      = (const float*)d_in[20];
    const float* fuse_w    = (const float*)d_in[21];
    const float* fuse_g    = (const float*)d_in[22];
    const float* fuse_b    = (const float*)d_in[23];
    const float* exp_w     = (const float*)d_in[24];
    const float* exp_g     = (const float*)d_in[25];
    const float* exp_b     = (const float*)d_in[26];
    const float* ctr_w     = (const float*)d_in[27];
    const float* reg_w     = (const float*)d_in[28];
    const float* cls_w     = (const float*)d_in[29];
    const float* cls_b     = (const float*)d_in[30];
    const float* scales    = (const float*)d_in[31];
    float* out = (float*)d_out;

    const long long nelem = (long long)out_size;

    k_fused<<<NBLOCKS, 256>>>(feats, nbr, Wsem, bsem,
                              fo_w, fo_g, fo_b,
                              cls_out_w, cls_out_g, cls_out_b,
                              up_w, up_g, up_b,
                              fuse_w, fuse_g, fuse_b,
                              exp_w, exp_g, exp_b,
                              ctr_w, reg_w, cls_w, cls_b, scales,
                              out, nelem);
}